// round 8
// baseline (speedup 1.0000x reference)
#include <cuda_runtime.h>
#include <cuda_bf16.h>

// Problem constants (fixed by setup_inputs)
#define CC      4
#define HH      256
#define WW      256
#define EE      32
#define OO      32
#define NN      125                  // (256-7)/2+1
#define NQ      (NN * NN)            // 15625
#define NQS     15632                // zT q-stride: mult of 8 -> 32B-aligned rows
#define DD      196                  // C*7*7 ; d = (c*7+r)*7 + s = row*7 + s
#define DIST_SCALE 10.0f
#define W_THR   1e-7f
#define MARGIN  1.9f                 // approx-gap select margin (>> worst bf16 err)
#define FULL    0xFFFFFFFFu

__device__ float          g_ZT[DD * NQS];   // transposed aggregation (~12.3MB)
__device__ __nv_bfloat16  g_XEH[NQ * EE];   // bf16 copy of xe (1MB)

// ---------------------------------------------------------------------------
// K0: xe (fp32) -> bf16 scratch. 250K float2 -> bf16x2.
// ---------------------------------------------------------------------------
__global__ __launch_bounds__(256) void cvt_kernel(const float* __restrict__ xe) {
    const int i = blockIdx.x * 256 + threadIdx.x;
    if (i < NQ * EE / 2) {
        const float2 v = reinterpret_cast<const float2*>(xe)[i];
        reinterpret_cast<__nv_bfloat162*>(g_XEH)[i] = __floats2bfloat162_rn(v.x, v.y);
    }
}

// ---------------------------------------------------------------------------
// K1: one query per warp, 8 warps/CTA.
//  p1a: APPROX distances from bf16 xe: 4 lanes/row (uint4 = 8 bf16),
//       8 candidates per LDG.128, 4 instrs total -> 32MB traffic.
//  p1b: EXACT fp32 recompute only for candidates within MARGIN of approx-min
//       (~1.2/query): 1 coalesced row-load + 5-shfl reduce each.
//  p2 : softmax over selected (missing mass < 4e-6), threshold W_THR.
//  p3 : row-grouped survivor gather from x (unchanged, measured good).
//  p4 : transposed store zT[d][q0..q0+7].
// ---------------------------------------------------------------------------
__global__ __launch_bounds__(256) void agg_kernel(const float* __restrict__ x,
                                                  const float* __restrict__ xe,
                                                  const float* __restrict__ ye,
                                                  const int*   __restrict__ inds) {
    const int lane = threadIdx.x & 31;
    const int wrp  = threadIdx.x >> 5;
    const int q0   = blockIdx.x * 8;
    const int q    = q0 + wrp;

    __shared__ float s_z [8][DD];
    __shared__ float s_d2[8][OO];
    __shared__ int   s_p [8][OO];

    if (q < NQ) {                                  // warp-uniform
        const float y_l = ye[q * EE + lane];
        const int   p_l = inds[q * OO + lane];

        // ---- p1a: approx distances (bf16) ----
        const int g2 = lane >> 2;                  // candidate within instr (0..7)
        const int c2 = lane & 3;                   // uint4 chunk of row (8 bf16)
        float ych[8];
#pragma unroll
        for (int j = 0; j < 8; j++)
            ych[j] = __shfl_sync(FULL, y_l, c2 * 8 + j);

        float acck[4];
#pragma unroll
        for (int k = 0; k < 4; k++) {
            const int po = __shfl_sync(FULL, p_l, k * 8 + g2);
            const uint4 u = *reinterpret_cast<const uint4*>(g_XEH + po * EE + c2 * 8);
            const float2 f0 = __bfloat1622float2(*reinterpret_cast<const __nv_bfloat162*>(&u.x));
            const float2 f1 = __bfloat1622float2(*reinterpret_cast<const __nv_bfloat162*>(&u.y));
            const float2 f2 = __bfloat1622float2(*reinterpret_cast<const __nv_bfloat162*>(&u.z));
            const float2 f3 = __bfloat1622float2(*reinterpret_cast<const __nv_bfloat162*>(&u.w));
            float a;
            float t0 = f0.x - ych[0]; a  = t0 * t0;
            float t1 = f0.y - ych[1]; a += t1 * t1;
            float t2 = f1.x - ych[2]; a += t2 * t2;
            float t3 = f1.y - ych[3]; a += t3 * t3;
            float t4 = f2.x - ych[4]; a += t4 * t4;
            float t5 = f2.y - ych[5]; a += t5 * t5;
            float t6 = f3.x - ych[6]; a += t6 * t6;
            float t7 = f3.y - ych[7]; a += t7 * t7;
            acck[k] = a;
        }
#pragma unroll
        for (int k = 0; k < 4; k++) {
            acck[k] += __shfl_xor_sync(FULL, acck[k], 1);
            acck[k] += __shfl_xor_sync(FULL, acck[k], 2);
        }
        if (c2 == 0) {
#pragma unroll
            for (int k = 0; k < 4; k++) s_d2[wrp][k * 8 + g2] = acck[k];
        }
        __syncwarp();
        const float d2a = s_d2[wrp][lane];
        __syncwarp();

        // select within margin of approx min
        float ma = d2a;
#pragma unroll
        for (int off = 16; off; off >>= 1)
            ma = fminf(ma, __shfl_xor_sync(FULL, ma, off));
        const unsigned sel = __ballot_sync(FULL, d2a <= ma + MARGIN);
        const int ns = __popc(sel);

        // ---- p1b: exact fp32 d2 for selected ----
        float mex = 3.4e38f;
        for (int si = 0; si < ns; si++) {
            const int lo = __fns(sel, 0, si + 1);
            const int po = __shfl_sync(FULL, p_l, lo);
            const float v = xe[po * EE + lane];
            const float t = v - y_l;
            float s2 = t * t;
#pragma unroll
            for (int off = 16; off; off >>= 1)
                s2 += __shfl_xor_sync(FULL, s2, off);
            if (lane == 0) { s_d2[wrp][si] = s2; s_p[wrp][si] = po; }
            mex = fminf(mex, s2);
        }
        __syncwarp();

        // ---- p2: softmax over selected ----
        float wsum = 0.f;
        for (int si = 0; si < ns; si++) {
            const float e = __expf(-DIST_SCALE * (s_d2[wrp][si] - mex));
            if (lane == 0) s_d2[wrp][si] = e;
            wsum += e;
        }
        __syncwarp();
        const float inv = 1.f / wsum;

        // ---- p3: row-grouped survivor gather from x ----
        const int row3 = lane >> 2;
        const int pair = lane & 3;
        int  offs[4];
        bool act [4];
        int  drow[4];
#pragma unroll
        for (int t = 0; t < 4; t++) {
            const int row = t * 8 + row3;
            act[t]  = (row < 28);
            const int rc = act[t] ? row : 0;
            const int c  = rc / 7;
            const int r  = rc - c * 7;
            offs[t] = c * (HH * WW) + r * WW + pair * 2;
            drow[t] = rc * 7;
        }

        float2 acc[4];
#pragma unroll
        for (int t = 0; t < 4; t++) acc[t] = make_float2(0.f, 0.f);

        for (int si = 0; si < ns; si++) {
            const float ws = s_d2[wrp][si] * inv;
            if (ws < W_THR) continue;              // warp-uniform
            const int po = s_p[wrp][si];
            const int pi = po / NN;
            const int pj = po - pi * NN;
            const int pb = pi * (2 * WW) + pj * 2;
#pragma unroll
            for (int t = 0; t < 4; t++) {
                if (act[t]) {
                    const float2 v = *reinterpret_cast<const float2*>(
                        x + offs[t] + pb);
                    acc[t].x += ws * v.x;
                    acc[t].y += ws * v.y;
                }
            }
        }

#pragma unroll
        for (int t = 0; t < 4; t++) {
            if (act[t]) {
                const int d0 = drow[t] + pair * 2;
                s_z[wrp][d0] = acc[t].x;
                if (pair < 3) s_z[wrp][d0 + 1] = acc[t].y;
            }
        }
    }

    __syncthreads();

    // ---- p4: transposed store zT[d][q0+qq] ----
#pragma unroll
    for (int mIdx = threadIdx.x; mIdx < DD * 8; mIdx += 256) {
        const int d  = mIdx >> 3;
        const int qq = mIdx & 7;
        if (q0 + qq < NQ)
            g_ZT[d * NQS + q0 + qq] = s_z[qq][d];
    }
}

// ---------------------------------------------------------------------------
// K2: fold. Staging unchanged; sum computes TWO pixels per thread (shared
// base b = t), killing even/odd half-mask duplication; float2 store.
// Writes every output element (poison-safe).
// ---------------------------------------------------------------------------
#define FW 132                        // [0..3]=0 pad, data 4..128, [129..131]=0 pad
__global__ __launch_bounds__(256) void fold_kernel(float* __restrict__ out) {
    const int c   = blockIdx.x >> 8;
    const int h   = blockIdx.x & 255;
    const int par = h & 1;

    __shared__ float s_rows[28][FW];

    const int lane = threadIdx.x & 31;
    const int wrp  = threadIdx.x >> 5;

    // staging: row rr = wrp + 8k
#pragma unroll
    for (int k = 0; k < 4; k++) {
        const int rr = wrp + 8 * k;
        if (rr >= 28) break;                      // warp-uniform
        const int ridx = rr / 7;
        const int s    = rr - ridx * 7;
        const int r    = par + 2 * ridx;
        const int i2   = h - r;
        const bool ok  = (r <= 6) && (i2 >= 0) && (i2 <= 2 * (NN - 1));
        float* dst = &s_rows[rr][0];
        if (ok) {
            const float* src = g_ZT + ((c * 7 + r) * 7 + s) * NQS + (i2 >> 1) * NN;
#pragma unroll
            for (int t = 0; t < 4; t++) {
                const int j = t * 32 + lane;
                if (j < 125) dst[4 + j] = src[j];
            }
        } else {
#pragma unroll
            for (int t = 0; t < 4; t++) {
                const int j = t * 32 + lane;
                if (j < 125) dst[4 + j] = 0.f;
            }
        }
        if (lane < 4) dst[lane] = 0.f;
        if (lane < 3) dst[129 + lane] = 0.f;
    }
    __syncthreads();

    // sum: thread t -> pixels w=2t (even: s=0,2,4,6) and w=2t+1 (odd: s=1,3,5)
    if (threadIdx.x < 128) {
        const int t = threadIdx.x;
        float acc0 = 0.f, acc1 = 0.f;
#pragma unroll
        for (int ridx = 0; ridx < 4; ridx++) {
            const int rb = ridx * 7;
#pragma unroll
            for (int si = 0; si < 4; si++)
                acc0 += s_rows[rb + 2 * si][4 + t - si];
#pragma unroll
            for (int si = 0; si < 3; si++)
                acc1 += s_rows[rb + 1 + 2 * si][4 + t - si];
        }
        reinterpret_cast<float2*>(out + blockIdx.x * 256)[t] =
            make_float2(acc0, acc1);
    }
}

// ---------------------------------------------------------------------------
extern "C" void kernel_launch(void* const* d_in, const int* in_sizes, int n_in,
                              void* d_out, int out_size) {
    const float* x    = (const float*)d_in[0];
    const float* xe   = (const float*)d_in[1];
    const float* ye   = (const float*)d_in[2];
    const int*   inds = (const int*)  d_in[3];
    float*       out  = (float*)d_out;
    (void)in_sizes; (void)n_in; (void)out_size;

    cvt_kernel<<<(NQ * EE / 2 + 255) / 256, 256>>>(xe);
    agg_kernel<<<(NQ + 7) / 8, 256>>>(x, xe, ye, inds);
    fold_kernel<<<CC * HH, 256>>>(out);
}

// round 9
// speedup vs baseline: 1.0885x; 1.0885x over previous
#include <cuda_runtime.h>

// Problem constants (fixed by setup_inputs)
#define CC      4
#define HH      256
#define WW      256
#define EE      32
#define OO      32
#define NN      125                  // (256-7)/2+1
#define NQ      (NN * NN)            // 15625
#define NQS     15632                // zT q-stride (pad: cols 15625..15631 garbage-ok)
#define DD      196                  // C*7*7 ; d = (c*7+r)*7 + s
#define DIST_SCALE 10.0f
#define W_THR   1e-7f
#define FULL    0xFFFFFFFFu

__device__ float g_ZT[DD * NQS];     // transposed aggregation zT[d][q] (~12.3MB)

// fold row tables: rr = ridx*7 + s  ->  ridx, s
__constant__ int c_ridx[28] = {0,0,0,0,0,0,0, 1,1,1,1,1,1,1, 2,2,2,2,2,2,2, 3,3,3,3,3,3,3};
__constant__ int c_s   [28] = {0,1,2,3,4,5,6, 0,1,2,3,4,5,6, 0,1,2,3,4,5,6, 0,1,2,3,4,5,6};

// ---------------------------------------------------------------------------
// K1: one query per warp, 8 warps/CTA (fp32 p1 — measured best).
// ---------------------------------------------------------------------------
__global__ __launch_bounds__(256) void agg_kernel(const float* __restrict__ x,
                                                  const float* __restrict__ xe,
                                                  const float* __restrict__ ye,
                                                  const int*   __restrict__ inds) {
    const int lane = threadIdx.x & 31;
    const int wrp  = threadIdx.x >> 5;
    const int q0   = blockIdx.x * 8;
    const int q    = q0 + wrp;

    __shared__ float s_z [8][DD];
    __shared__ float s_d2[8][OO];

    if (q < NQ) {                                  // warp-uniform (guards input OOB)
        // ---- p1: coalesced distances ----
        const int g  = lane >> 3;
        const int ch = lane & 7;
        const float4 y4 = reinterpret_cast<const float4*>(ye + q * EE)[ch];
        const int p_l   = inds[q * OO + lane];

        float acck[8];
#pragma unroll
        for (int k = 0; k < 8; k++) {
            const int po = __shfl_sync(FULL, p_l, k * 4 + g);
            const float4 v = reinterpret_cast<const float4*>(xe + po * EE)[ch];
            const float dx = v.x - y4.x, dy = v.y - y4.y;
            const float dz = v.z - y4.z, dw = v.w - y4.w;
            acck[k] = dx * dx + dy * dy + dz * dz + dw * dw;
        }
#pragma unroll
        for (int k = 0; k < 8; k++) {
            acck[k] += __shfl_xor_sync(FULL, acck[k], 1);
            acck[k] += __shfl_xor_sync(FULL, acck[k], 2);
            acck[k] += __shfl_xor_sync(FULL, acck[k], 4);
        }
        if (ch == 0) {
#pragma unroll
            for (int k = 0; k < 8; k++) s_d2[wrp][k * 4 + g] = acck[k];
        }
        __syncwarp();
        const float d2 = s_d2[wrp][lane];

        // ---- p2: softmax + threshold ----
        float m = d2;
#pragma unroll
        for (int off = 16; off; off >>= 1)
            m = fminf(m, __shfl_xor_sync(FULL, m, off));
        const float ev = __expf(-DIST_SCALE * (d2 - m));
        float sum = ev;
#pragma unroll
        for (int off = 16; off; off >>= 1)
            sum += __shfl_xor_sync(FULL, sum, off);
        const float w = ev / sum;

        const unsigned surv = __ballot_sync(FULL, w >= W_THR);
        const int ks = __popc(surv);

        // ---- p3: row-grouped survivor gather from x ----
        const int row3 = lane >> 2;
        const int pair = lane & 3;
        int  offs[4];
        bool act [4];
        int  drow[4];
#pragma unroll
        for (int t = 0; t < 4; t++) {
            const int row = t * 8 + row3;
            act[t]  = (row < 28);
            const int rc = act[t] ? row : 0;
            const int c  = rc / 7;
            const int r  = rc - c * 7;
            offs[t] = c * (HH * WW) + r * WW + pair * 2;
            drow[t] = rc * 7;
        }

        float2 acc[4];
#pragma unroll
        for (int t = 0; t < 4; t++) acc[t] = make_float2(0.f, 0.f);

        for (int s = 0; s < ks; s++) {
            const int   lo = __fns(surv, 0, s + 1);
            const float ws = __shfl_sync(FULL, w,   lo);
            const int   po = __shfl_sync(FULL, p_l, lo);
            const int   pi = po / NN;
            const int   pj = po - pi * NN;
            const int   pb = pi * (2 * WW) + pj * 2;
#pragma unroll
            for (int t = 0; t < 4; t++) {
                if (act[t]) {
                    const float2 v = *reinterpret_cast<const float2*>(
                        x + offs[t] + pb);
                    acc[t].x += ws * v.x;
                    acc[t].y += ws * v.y;
                }
            }
        }

#pragma unroll
        for (int t = 0; t < 4; t++) {
            if (act[t]) {
                const int d0 = drow[t] + pair * 2;
                s_z[wrp][d0] = acc[t].x;
                if (pair < 3) s_z[wrp][d0 + 1] = acc[t].y;
            }
        }
    }

    __syncthreads();

    // ---- p4: transposed store, UNGUARDED (zT q-pad absorbs garbage) ----
    // 1568 = 256*6 + 32 ; warp 0 takes the tail chunk.
    const int tid = threadIdx.x;
#pragma unroll
    for (int k = 0; k < 6; k++) {
        const int mIdx = tid + 256 * k;
        const int d  = mIdx >> 3;
        const int qq = mIdx & 7;
        g_ZT[d * NQS + q0 + qq] = s_z[qq][d];
    }
    if (tid < 32) {
        const int mIdx = tid + 1536;
        const int d  = mIdx >> 3;
        const int qq = mIdx & 7;
        g_ZT[d * NQS + q0 + qq] = s_z[qq][d];
    }
}

// ---------------------------------------------------------------------------
// K2: fold, de-bloated.
//  Staging: warp<->row map via constant tables, 4 UNGUARDED coalesced LDG.32
//  (overshoot j=125..127 lands in pad slots 129..131, re-zeroed after
//   __syncwarp; reads stay in-bounds: max index 15627 < NQS).
//  Sum: 2 pixels/thread, 16+12 immediate-offset LDS, float2 store.
// ---------------------------------------------------------------------------
#define FW 132                        // [0..3]=0 pad, data 4..128, [129..131]=0 pad
__global__ __launch_bounds__(256) void fold_kernel(float* __restrict__ out) {
    const int c   = blockIdx.x >> 8;
    const int h   = blockIdx.x & 255;
    const int par = h & 1;

    __shared__ float s_rows[28][FW];

    const int lane = threadIdx.x & 31;
    const int wrp  = threadIdx.x >> 5;

#pragma unroll
    for (int k = 0; k < 4; k++) {
        const int rr = wrp + 8 * k;
        if (rr >= 28) break;                      // warp-uniform (only k=3,wrp>=4)
        const int ridx = c_ridx[rr];
        const int s    = c_s[rr];
        const int r    = par + 2 * ridx;
        const int i2   = h - r;
        float* dst = &s_rows[rr][0];
        if ((r <= 6) && (i2 >= 0) && (i2 <= 2 * (NN - 1))) {
            const float* src = g_ZT + ((c * 7 + r) * 7 + s) * NQS + (i2 >> 1) * NN;
            dst[4 + lane]       = src[lane];
            dst[4 + lane + 32]  = src[lane + 32];
            dst[4 + lane + 64]  = src[lane + 64];
            dst[4 + lane + 96]  = src[lane + 96];
        } else {
            dst[4 + lane]       = 0.f;
            dst[4 + lane + 32]  = 0.f;
            dst[4 + lane + 64]  = 0.f;
            dst[4 + lane + 96]  = 0.f;
        }
        __syncwarp();
        if (lane < 4) dst[lane] = 0.f;            // left pad
        if (lane < 3) dst[129 + lane] = 0.f;      // right pad (kills overshoot)
    }
    __syncthreads();

    // sum: thread t -> pixels w=2t (s=0,2,4,6) and w=2t+1 (s=1,3,5)
    if (threadIdx.x < 128) {
        const int t = threadIdx.x;
        float acc0 = 0.f, acc1 = 0.f;
#pragma unroll
        for (int ridx = 0; ridx < 4; ridx++) {
            const int rb = ridx * 7;
#pragma unroll
            for (int si = 0; si < 4; si++)
                acc0 += s_rows[rb + 2 * si][4 + t - si];
#pragma unroll
            for (int si = 0; si < 3; si++)
                acc1 += s_rows[rb + 1 + 2 * si][4 + t - si];
        }
        reinterpret_cast<float2*>(out + blockIdx.x * 256)[t] =
            make_float2(acc0, acc1);
    }
}

// ---------------------------------------------------------------------------
extern "C" void kernel_launch(void* const* d_in, const int* in_sizes, int n_in,
                              void* d_out, int out_size) {
    const float* x    = (const float*)d_in[0];
    const float* xe   = (const float*)d_in[1];
    const float* ye   = (const float*)d_in[2];
    const int*   inds = (const int*)  d_in[3];
    float*       out  = (float*)d_out;
    (void)in_sizes; (void)n_in; (void)out_size;

    agg_kernel<<<(NQ + 7) / 8, 256>>>(x, xe, ye, inds);
    fold_kernel<<<CC * HH, 256>>>(out);
}